// round 6
// baseline (speedup 1.0000x reference)
#include <cuda_runtime.h>

#define SEQ     1024
#define HDIM    640
#define G4      2560
#define NNODES  1024
#define NEDGES  16384
#define BSZ     16
#define NCTA_REC 128
#define MAXSPLIT 8

// ---------------- scratch (device globals; no runtime allocation) ----------------
__device__ float g_xWp[MAXSPLIT][SEQ * G4]; // 84 MB  split-K partials
__device__ float g_xW[SEQ * G4];            // 10.5 MB reduced LSTM input projections
__device__ float g_bufA[SEQ * HDIM];
__device__ float g_bufB[SEQ * HDIM];
__device__ float g_gh[NNODES * 320];
__device__ float g_gy[NNODES * 320];
__device__ float g_Wt[640 * 320];
__device__ int   g_deg[NNODES];
__device__ float g_dinv[NNODES];
__device__ float g_selfnorm[NNODES];
__device__ float g_enorm[NEDGES];
__device__ unsigned g_flag[NCTA_REC * 8];   // 1 flag per rec-CTA, padded to 32B

__device__ __forceinline__ float fsigmoid(float x) { return 1.f / (1.f + __expf(-x)); }
__device__ __forceinline__ float ftanh(float x) { return 2.f / (1.f + __expf(-2.f * x)) - 1.f; }

// ---------------- split-K fp32 NT GEMM: partial C_z = A[:,kz]*B[:,kz]^T ----------------
// BM=128 BN=128 BK=16, 256 threads, 8x8/thread, double-buffered. M%128==0, N%128==0.
// blockIdx.z = split id; K range [z*Kc, min(K,(z+1)*Kc)); Kc % 4 == 0 required.
__global__ __launch_bounds__(256) void sgemm128_split(
    const float* __restrict__ A, const float* __restrict__ B,
    float* __restrict__ Cbase, int M, int N, int K, int Kc)
{
    __shared__ float As[2][16][128];
    __shared__ float Bs[2][16][128];
    const int tid = threadIdx.x;
    const int z = blockIdx.z;
    const int k0 = z * Kc;
    const int kend = min(K, k0 + Kc);
    float* __restrict__ C = Cbase + (size_t)z * ((size_t)SEQ * G4);
    const int m0 = blockIdx.y * 128, n0 = blockIdx.x * 128;
    const int rowg = (tid >> 4) << 3;
    const int colg = (tid & 15) << 3;

    float acc[8][8];
#pragma unroll
    for (int i = 0; i < 8; i++)
#pragma unroll
        for (int j = 0; j < 8; j++) acc[i][j] = 0.f;

    const int ntiles = (kend - k0 + 15) >> 4;

    auto ldtile = [&](const float* __restrict__ P, int base_row, int kb, float4* out) {
#pragma unroll
        for (int i = 0; i < 2; i++) {
            int fid = tid * 2 + i;
            int r = fid >> 2, kk = (fid & 3) << 2;
            float4 v = make_float4(0.f, 0.f, 0.f, 0.f);
            const float* p = P + (size_t)(base_row + r) * K + kb + kk;
            if (kb + kk + 3 < kend) v = *(const float4*)p;
            else {
                if (kb + kk + 0 < kend) v.x = p[0];
                if (kb + kk + 1 < kend) v.y = p[1];
                if (kb + kk + 2 < kend) v.z = p[2];
            }
            out[i] = v;
        }
    };
    auto sttile = [&](float (*S)[128], const float4* v) {
#pragma unroll
        for (int i = 0; i < 2; i++) {
            int fid = tid * 2 + i;
            int r = fid >> 2, kk = (fid & 3) << 2;
            S[kk + 0][r] = v[i].x; S[kk + 1][r] = v[i].y;
            S[kk + 2][r] = v[i].z; S[kk + 3][r] = v[i].w;
        }
    };

    float4 pa[2], pb[2];
    ldtile(A, m0, k0, pa);
    ldtile(B, n0, k0, pb);
    sttile(As[0], pa);
    sttile(Bs[0], pb);
    __syncthreads();

    for (int kt = 0; kt < ntiles; kt++) {
        const int cur = kt & 1;
        if (kt + 1 < ntiles) {
            ldtile(A, m0, k0 + (kt + 1) * 16, pa);
            ldtile(B, n0, k0 + (kt + 1) * 16, pb);
        }
        const float (*Ac)[128] = As[cur];
        const float (*Bc)[128] = Bs[cur];
#pragma unroll
        for (int k = 0; k < 16; k++) {
            float4 a0 = *(const float4*)&Ac[k][rowg];
            float4 a1 = *(const float4*)&Ac[k][rowg + 4];
            float4 b0 = *(const float4*)&Bc[k][colg];
            float4 b1 = *(const float4*)&Bc[k][colg + 4];
            float a[8]  = {a0.x, a0.y, a0.z, a0.w, a1.x, a1.y, a1.z, a1.w};
            float bb[8] = {b0.x, b0.y, b0.z, b0.w, b1.x, b1.y, b1.z, b1.w};
#pragma unroll
            for (int i = 0; i < 8; i++)
#pragma unroll
                for (int j = 0; j < 8; j++)
                    acc[i][j] += a[i] * bb[j];
        }
        if (kt + 1 < ntiles) {
            sttile(As[1 - cur], pa);
            sttile(Bs[1 - cur], pb);
        }
        __syncthreads();
    }

#pragma unroll
    for (int i = 0; i < 8; i++) {
        const int m = m0 + rowg + i;
        float* cp = C + (size_t)m * N + n0 + colg;
#pragma unroll
        for (int j = 0; j < 8; j++) cp[j] = acc[i][j];
    }
}

// ---------------- sum split partials + fold biases (exactly SEQ*G4/4 float4 threads) ----------------
__global__ void reduce_splits(const float* __restrict__ bufs, float* __restrict__ C,
                              const float* __restrict__ b1, const float* __restrict__ b2,
                              int s, int N)
{
    int idx = blockIdx.x * blockDim.x + threadIdx.x;
    size_t base = (size_t)idx * 4;
    float4 acc = *(const float4*)(bufs + base);
    for (int i = 1; i < s; i++) {
        float4 v = *(const float4*)(bufs + (size_t)i * ((size_t)SEQ * G4) + base);
        acc.x += v.x; acc.y += v.y; acc.z += v.z; acc.w += v.w;
    }
    int n = (int)(base % (size_t)N);
    float4 u1 = *(const float4*)(b1 + n);
    float4 u2 = *(const float4*)(b2 + n);
    acc.x += u1.x + u2.x; acc.y += u1.y + u2.y;
    acc.z += u1.z + u2.z; acc.w += u1.w + u2.w;
    *(float4*)(C + base) = acc;
}

// ---------------- generic fp32 NT GEMM (GCN path, small N) ----------------
__global__ __launch_bounds__(256) void sgemm_nt(
    const float* __restrict__ A, const float* __restrict__ B,
    float* __restrict__ C, int M, int N, int K)
{
    __shared__ float As[16][128];
    __shared__ float Bs[16][64];
    const int tx = threadIdx.x, ty = threadIdx.y;
    const int tid = ty * 16 + tx;
    const int m0 = blockIdx.y * 128, n0 = blockIdx.x * 64;

    float acc[8][4];
#pragma unroll
    for (int i = 0; i < 8; i++)
#pragma unroll
        for (int j = 0; j < 4; j++) acc[i][j] = 0.f;

    const bool k4ok = ((K & 3) == 0);
    const int ntiles = (K + 15) >> 4;

    for (int kt = 0; kt < ntiles; kt++) {
        const int kb = kt * 16;
#pragma unroll
        for (int i = 0; i < 2; i++) {
            int fid = tid * 2 + i;
            int r = fid >> 2;
            int kk = (fid & 3) << 2;
            float4 v = make_float4(0.f, 0.f, 0.f, 0.f);
            if (m0 + r < M) {
                const float* ap = A + (size_t)(m0 + r) * K + kb + kk;
                if (k4ok && kb + kk + 3 < K) v = *(const float4*)ap;
                else {
                    if (kb + kk + 0 < K) v.x = ap[0];
                    if (kb + kk + 1 < K) v.y = ap[1];
                    if (kb + kk + 2 < K) v.z = ap[2];
                    if (kb + kk + 3 < K) v.w = ap[3];
                }
            }
            As[kk + 0][r] = v.x; As[kk + 1][r] = v.y;
            As[kk + 2][r] = v.z; As[kk + 3][r] = v.w;
        }
        {
            int r = tid >> 2;
            int kk = (tid & 3) << 2;
            float4 v = make_float4(0.f, 0.f, 0.f, 0.f);
            if (n0 + r < N) {
                const float* bp = B + (size_t)(n0 + r) * K + kb + kk;
                if (k4ok && kb + kk + 3 < K) v = *(const float4*)bp;
                else {
                    if (kb + kk + 0 < K) v.x = bp[0];
                    if (kb + kk + 1 < K) v.y = bp[1];
                    if (kb + kk + 2 < K) v.z = bp[2];
                    if (kb + kk + 3 < K) v.w = bp[3];
                }
            }
            Bs[kk + 0][r] = v.x; Bs[kk + 1][r] = v.y;
            Bs[kk + 2][r] = v.z; Bs[kk + 3][r] = v.w;
        }
        __syncthreads();
#pragma unroll
        for (int k = 0; k < 16; k++) {
            float4 b4 = *(const float4*)&Bs[k][tx * 4];
            float4 a0 = *(const float4*)&As[k][ty * 8];
            float4 a1 = *(const float4*)&As[k][ty * 8 + 4];
            float a[8] = {a0.x, a0.y, a0.z, a0.w, a1.x, a1.y, a1.z, a1.w};
            float bb[4] = {b4.x, b4.y, b4.z, b4.w};
#pragma unroll
            for (int i = 0; i < 8; i++)
#pragma unroll
                for (int j = 0; j < 4; j++)
                    acc[i][j] += a[i] * bb[j];
        }
        __syncthreads();
    }
#pragma unroll
    for (int i = 0; i < 8; i++) {
        int m = m0 + ty * 8 + i;
        if (m >= M) continue;
#pragma unroll
        for (int j = 0; j < 4; j++) {
            int n = n0 + tx * 4 + j;
            if (n < N) C[(size_t)m * N + n] = acc[i][j];
        }
    }
}

// ---------------- flag reset ----------------
__global__ void zero_flags() {
    int i = blockIdx.x * blockDim.x + threadIdx.x;
    if (i < NCTA_REC * 8) g_flag[i] = 0u;
}

// ---------------- persistent LSTM recurrence (per-CTA monotonic flags) ----------------
// 128 CTAs x 640 threads. CTA k owns hidden units [5k,5k+5); warp w: unit u=w>>2,
// gate g=w&3, Whh row in registers. CTA k publishes step t by st.release g_flag[k*8]=t+1
// (no atomics -> no same-address L2 serialization). Warp 0 polls all 128 padded flags
// with relaxed loads + ballot; fence.acq_rel.gpu on detect; bar.sync propagates.
__global__ __launch_bounds__(640, 1) void lstm_rec(
    const float* __restrict__ xW,   // [1024, 2560] (biases folded in)
    const float* __restrict__ Whh,  // [2560, 640]
    float* __restrict__ seq_out)    // [1024, 640]
{
    __shared__ float h_s[640];
    __shared__ float dots[5][4];
    __shared__ float c_s[5];

    const int tid = threadIdx.x;
    const int w = tid >> 5, l = tid & 31;
    const int k = blockIdx.x;
    const int u = w >> 2;
    const int gsel = w & 3;
    const int uglob = 5 * k + u;
    const int row = gsel * 640 + uglob;

    float wreg[20];
    const float* wp = Whh + (size_t)row * 640 + 20 * l;
#pragma unroll
    for (int i = 0; i < 20; i++) wreg[i] = wp[i];
    if (tid < 5) c_s[tid] = 0.f;
    unsigned* myflag = g_flag + k * 8;
    const unsigned* pollp = g_flag + l * 32;   // lane l watches flags l*4..l*4+3 (stride 8 words)
    __syncthreads();

    for (int t = 0; t < SEQ; t++) {
        // gate threads prefetch xW operands before the wait (off critical path)
        float xg0 = 0.f, xg1 = 0.f, xg2 = 0.f, xg3 = 0.f;
        if (tid < 5) {
            const float* xwt = xW + (size_t)t * G4 + 5 * k + tid;
            xg0 = __ldg(xwt);
            xg1 = __ldg(xwt + 640);
            xg2 = __ldg(xwt + 1280);
            xg3 = __ldg(xwt + 1920);
        }

        float acc = 0.f;
        if (t > 0) {
            if (w == 0) {
                const unsigned tt = (unsigned)t;
                for (;;) {
                    unsigned f0, f1, f2, f3;
                    asm volatile("ld.relaxed.gpu.global.u32 %0, [%1];" : "=r"(f0) : "l"(pollp)      : "memory");
                    asm volatile("ld.relaxed.gpu.global.u32 %0, [%1];" : "=r"(f1) : "l"(pollp + 8)  : "memory");
                    asm volatile("ld.relaxed.gpu.global.u32 %0, [%1];" : "=r"(f2) : "l"(pollp + 16) : "memory");
                    asm volatile("ld.relaxed.gpu.global.u32 %0, [%1];" : "=r"(f3) : "l"(pollp + 24) : "memory");
                    bool ok = (f0 >= tt) & (f1 >= tt) & (f2 >= tt) & (f3 >= tt);
                    if (__ballot_sync(0xffffffffu, ok) == 0xffffffffu) break;
                }
                asm volatile("fence.acq_rel.gpu;" ::: "memory");
            }
            __syncthreads();
            h_s[tid] = __ldcg(seq_out + (size_t)(t - 1) * 640 + tid);
            __syncthreads();
            const float4* hp = (const float4*)(h_s + 20 * l);
#pragma unroll
            for (int i = 0; i < 5; i++) {
                float4 v = hp[i];
                acc += wreg[4 * i + 0] * v.x + wreg[4 * i + 1] * v.y
                     + wreg[4 * i + 2] * v.z + wreg[4 * i + 3] * v.w;
            }
        }
#pragma unroll
        for (int off = 16; off > 0; off >>= 1)
            acc += __shfl_down_sync(0xffffffffu, acc, off);
        if (l == 0) dots[u][gsel] = acc;
        __syncthreads();

        if (w == 0) {
            if (l < 5) {
                const int uu = l;
                const int ug = 5 * k + uu;
                float gi = xg0 + dots[uu][0];
                float gf = xg1 + dots[uu][1];
                float gg = xg2 + dots[uu][2];
                float go = xg3 + dots[uu][3];
                float iv = fsigmoid(gi);
                float fv = fsigmoid(gf);
                float gv = ftanh(gg);
                float ov = fsigmoid(go);
                float c = fv * c_s[uu] + iv * gv;
                c_s[uu] = c;
                seq_out[(size_t)t * 640 + ug] = ov * ftanh(c);
            }
            __syncwarp(0xffffffffu);
            if (l == 0) {
                asm volatile("st.release.gpu.global.u32 [%0], %1;"
                             :: "l"(myflag), "r"((unsigned)(t + 1)) : "memory");
            }
        }
        // no trailing CTA barrier needed: non-gate warps park at the next
        // iteration's __syncthreads until warp 0 finishes gates+publish+poll.
    }
}

// ---------------- graph prep ----------------
__global__ void zero_deg(int* deg) {
    int i = blockIdx.x * blockDim.x + threadIdx.x;
    if (i < NNODES) deg[i] = 0;
}
__global__ void count_deg(const int* __restrict__ dst, int* deg) {
    int e = blockIdx.x * blockDim.x + threadIdx.x;
    if (e < NEDGES) atomicAdd(&deg[dst[e]], 1);
}
__global__ void finalize_deg(const int* __restrict__ deg, float* dinv, float* selfnorm) {
    int i = blockIdx.x * blockDim.x + threadIdx.x;
    if (i < NNODES) {
        float d = rsqrtf((float)(deg[i] + 1));
        dinv[i] = d;
        selfnorm[i] = d * d;
    }
}
__global__ void edge_norm(const int* __restrict__ src, const int* __restrict__ dst,
                          const float* __restrict__ dinv, float* enorm) {
    int e = blockIdx.x * blockDim.x + threadIdx.x;
    if (e < NEDGES) enorm[e] = dinv[src[e]] * dinv[dst[e]];
}
__global__ void transpose_k(const float* __restrict__ W, float* __restrict__ Wt,
                            int Cin, int Cout) {
    int idx = blockIdx.x * blockDim.x + threadIdx.x;
    if (idx < Cin * Cout) {
        int i = idx / Cout, o = idx % Cout;
        Wt[o * Cin + i] = W[idx];
    }
}

// ---------------- GCN scatter ----------------
__global__ void scatter_init(const float* __restrict__ h, const float* __restrict__ selfnorm,
                             float* __restrict__ y, int C) {
    int idx = blockIdx.x * blockDim.x + threadIdx.x;
    if (idx < NNODES * C) {
        int i = idx / C;
        y[idx] = selfnorm[i] * h[idx];
    }
}
__global__ void scatter_edges(const float* __restrict__ h, const float* __restrict__ enorm,
                              const int* __restrict__ src, const int* __restrict__ dst,
                              float* __restrict__ y, int C) {
    int idx = blockIdx.x * blockDim.x + threadIdx.x;
    if (idx < NEDGES * C) {
        int e = idx / C, c = idx - e * C;
        atomicAdd(&y[dst[e] * C + c], enorm[e] * h[src[e] * C + c]);
    }
}

// ---------------- bias + leaky + batchnorm (per-column CTA) ----------------
__global__ void bias_leaky_bn(const float* __restrict__ y, const float* __restrict__ b,
                              float* __restrict__ out, int C) {
    const int c = blockIdx.x;
    const int tid = threadIdx.x;
    const float bias = b[c];
    float s = 0.f, sq = 0.f;
    for (int r = tid; r < NNODES; r += 256) {
        float v = y[r * C + c] + bias;
        v = (v > 0.f) ? v : 0.01f * v;
        s += v; sq += v * v;
    }
    __shared__ float rs[256], rq[256];
    rs[tid] = s; rq[tid] = sq;
    __syncthreads();
    for (int o = 128; o > 0; o >>= 1) {
        if (tid < o) { rs[tid] += rs[tid + o]; rq[tid] += rq[tid + o]; }
        __syncthreads();
    }
    float mean = rs[0] * (1.f / NNODES);
    float var = rq[0] * (1.f / NNODES) - mean * mean;
    float rstd = rsqrtf(var + 1e-5f);
    for (int r = tid; r < NNODES; r += 256) {
        float v = y[r * C + c] + bias;
        v = (v > 0.f) ? v : 0.01f * v;
        out[r * C + c] = (v - mean) * rstd;
    }
}

// ---------------- head: segment sum + concat + 3 FC ----------------
__global__ void head_kernel(const float* __restrict__ x,
                            const float* __restrict__ gender, const float* __restrict__ handed,
                            const float* __restrict__ W1, const float* __restrict__ b1,
                            const float* __restrict__ W2, const float* __restrict__ b2,
                            const float* __restrict__ W3, const float* __restrict__ b3,
                            float* __restrict__ out) {
    const int b = blockIdx.x;
    const int tid = threadIdx.x;
    __shared__ float feat[52];
    __shared__ float y1[32], y2[16];
    if (tid < 50) {
        float s = 0.f;
        for (int r = 0; r < 64; r++) s += x[(b * 64 + r) * 50 + tid];
        feat[tid] = s;
    }
    if (tid == 50) feat[50] = gender[b];
    if (tid == 51) feat[51] = handed[b];
    __syncthreads();
    if (tid < 32) {
        float s = b1[tid];
        for (int i = 0; i < 52; i++) s += feat[i] * W1[tid * 52 + i];
        y1[tid] = s;
    }
    __syncthreads();
    if (tid < 16) {
        float s = b2[tid];
        for (int i = 0; i < 32; i++) s += y1[i] * W2[tid * 32 + i];
        y2[tid] = s;
    }
    __syncthreads();
    if (tid == 0) {
        float s = b3[0];
        for (int i = 0; i < 16; i++) s += y2[i] * W3[i];
        out[b] = s;
    }
}

// ---------------- host ----------------
extern "C" void kernel_launch(void* const* d_in, const int* in_sizes, int n_in,
                              void* d_out, int out_size) {
    const float* x_in   = (const float*)d_in[0];
    const int*   eidx   = (const int*)d_in[1];
    const float* gender = (const float*)d_in[2];
    const float* handed = (const float*)d_in[3];
    const float* Wih[3] = {(const float*)d_in[4], (const float*)d_in[8],  (const float*)d_in[12]};
    const float* Whh[3] = {(const float*)d_in[5], (const float*)d_in[9],  (const float*)d_in[13]};
    const float* bih[3] = {(const float*)d_in[6], (const float*)d_in[10], (const float*)d_in[14]};
    const float* bhh[3] = {(const float*)d_in[7], (const float*)d_in[11], (const float*)d_in[15]};
    const float* gcnW[4] = {(const float*)d_in[16], (const float*)d_in[18], (const float*)d_in[20], (const float*)d_in[22]};
    const float* gcnB[4] = {(const float*)d_in[17], (const float*)d_in[19], (const float*)d_in[21], (const float*)d_in[23]};
    const float* fcW[3] = {(const float*)d_in[24], (const float*)d_in[26], (const float*)d_in[28]};
    const float* fcB[3] = {(const float*)d_in[25], (const float*)d_in[27], (const float*)d_in[29]};

    float *xWp, *xW, *bufA, *bufB, *gh, *gy, *Wt, *dinv, *selfnorm, *enorm;
    int* deg;
    cudaGetSymbolAddress((void**)&xWp, g_xWp);
    cudaGetSymbolAddress((void**)&xW, g_xW);
    cudaGetSymbolAddress((void**)&bufA, g_bufA);
    cudaGetSymbolAddress((void**)&bufB, g_bufB);
    cudaGetSymbolAddress((void**)&gh, g_gh);
    cudaGetSymbolAddress((void**)&gy, g_gy);
    cudaGetSymbolAddress((void**)&Wt, g_Wt);
    cudaGetSymbolAddress((void**)&deg, g_deg);
    cudaGetSymbolAddress((void**)&dinv, g_dinv);
    cudaGetSymbolAddress((void**)&selfnorm, g_selfnorm);
    cudaGetSymbolAddress((void**)&enorm, g_enorm);

    const int* src = eidx;
    const int* dst = eidx + NEDGES;
    dim3 tb(16, 16);
    const int nred = (SEQ * G4) / 4 / 256;   // 2560 CTAs, exact

    // ---- LSTM layer 0 (K=8500, split-K s=8, Kc=1064 multiple of 4) ----
    sgemm128_split<<<dim3(G4 / 128, SEQ / 128, 8), 256>>>(x_in, Wih[0], xWp, SEQ, G4, 8500, 1064);
    reduce_splits<<<nred, 256>>>(xWp, xW, bih[0], bhh[0], 8, G4);
    zero_flags<<<4, 256>>>();
    lstm_rec<<<NCTA_REC, 640>>>(xW, Whh[0], bufA);

    // ---- LSTM layer 1 (K=640, split-K s=2) ----
    sgemm128_split<<<dim3(G4 / 128, SEQ / 128, 2), 256>>>(bufA, Wih[1], xWp, SEQ, G4, HDIM, 320);
    reduce_splits<<<nred, 256>>>(xWp, xW, bih[1], bhh[1], 2, G4);
    zero_flags<<<4, 256>>>();
    lstm_rec<<<NCTA_REC, 640>>>(xW, Whh[1], bufB);

    // ---- LSTM layer 2 ----
    sgemm128_split<<<dim3(G4 / 128, SEQ / 128, 2), 256>>>(bufB, Wih[2], xWp, SEQ, G4, HDIM, 320);
    reduce_splits<<<nred, 256>>>(xWp, xW, bih[2], bhh[2], 2, G4);
    zero_flags<<<4, 256>>>();
    lstm_rec<<<NCTA_REC, 640>>>(xW, Whh[2], bufA);

    // ---- graph prep ----
    zero_deg<<<4, 256>>>(deg);
    count_deg<<<NEDGES / 256, 256>>>(dst, deg);
    finalize_deg<<<4, 256>>>(deg, dinv, selfnorm);
    edge_norm<<<NEDGES / 256, 256>>>(src, dst, dinv, enorm);

    // ---- GCN layers ----
    const int cins[4]  = {640, 320, 180, 90};
    const int couts[4] = {320, 180, 90, 50};
    float* xcur = bufA;
    float* xnext = bufB;
    for (int l = 0; l < 4; l++) {
        int Cin = cins[l], Cout = couts[l];
        transpose_k<<<(Cin * Cout + 255) / 256, 256>>>(gcnW[l], Wt, Cin, Cout);
        sgemm_nt<<<dim3((Cout + 63) / 64, NNODES / 128), tb>>>(xcur, Wt, gh, NNODES, Cout, Cin);
        scatter_init<<<(NNODES * Cout + 255) / 256, 256>>>(gh, selfnorm, gy, Cout);
        scatter_edges<<<(NEDGES * Cout + 255) / 256, 256>>>(gh, enorm, src, dst, gy, Cout);
        bias_leaky_bn<<<Cout, 256>>>(gy, gcnB[l], xnext, Cout);
        float* tmp = xcur; xcur = xnext; xnext = tmp;
    }

    // ---- head ----
    head_kernel<<<BSZ, 64>>>(xcur, gender, handed,
                             fcW[0], fcB[0], fcW[1], fcB[1], fcW[2], fcB[2],
                             (float*)d_out);
}

// round 7
// speedup vs baseline: 1.6424x; 1.6424x over previous
#include <cuda_runtime.h>

#define SEQ     1024
#define HDIM    640
#define G4      2560
#define NNODES  1024
#define NEDGES  16384
#define BSZ     16
#define NCTA_REC 128
#define MAXSPLIT 8

// ---------------- scratch (device globals; no runtime allocation) ----------------
__device__ float g_xWp[MAXSPLIT][SEQ * G4]; // 84 MB  split-K partials
__device__ float g_xW[SEQ * G4];            // 10.5 MB reduced LSTM input projections
__device__ float g_bufA[SEQ * HDIM];
__device__ float g_bufB[SEQ * HDIM];
__device__ float g_gh[NNODES * 320];
__device__ float g_gy[NNODES * 320];
__device__ float g_Wt[640 * 320];
__device__ int   g_deg[NNODES];
__device__ float g_dinv[NNODES];
__device__ float g_selfnorm[NNODES];
__device__ float g_enorm[NEDGES];
__device__ unsigned g_cnt[SEQ];             // per-timestep publish counters

// ---------------- split-K fp32 NT GEMM: partial C_z = A[:,kz]*B[:,kz]^T ----------------
// BM=128 BN=128 BK=16, 256 threads, 8x8/thread, double-buffered. M%128==0, N%128==0.
// blockIdx.z = split id; K range [z*Kc, min(K,(z+1)*Kc)); Kc % 4 == 0 required.
__global__ __launch_bounds__(256) void sgemm128_split(
    const float* __restrict__ A, const float* __restrict__ B,
    float* __restrict__ Cbase, int M, int N, int K, int Kc)
{
    __shared__ float As[2][16][128];
    __shared__ float Bs[2][16][128];
    const int tid = threadIdx.x;
    const int z = blockIdx.z;
    const int k0 = z * Kc;
    const int kend = min(K, k0 + Kc);
    float* __restrict__ C = Cbase + (size_t)z * ((size_t)SEQ * G4);
    const int m0 = blockIdx.y * 128, n0 = blockIdx.x * 128;
    const int rowg = (tid >> 4) << 3;
    const int colg = (tid & 15) << 3;

    float acc[8][8];
#pragma unroll
    for (int i = 0; i < 8; i++)
#pragma unroll
        for (int j = 0; j < 8; j++) acc[i][j] = 0.f;

    const int ntiles = (kend - k0 + 15) >> 4;

    auto ldtile = [&](const float* __restrict__ P, int base_row, int kb, float4* out) {
#pragma unroll
        for (int i = 0; i < 2; i++) {
            int fid = tid * 2 + i;
            int r = fid >> 2, kk = (fid & 3) << 2;
            float4 v = make_float4(0.f, 0.f, 0.f, 0.f);
            const float* p = P + (size_t)(base_row + r) * K + kb + kk;
            if (kb + kk + 3 < kend) v = *(const float4*)p;
            else {
                if (kb + kk + 0 < kend) v.x = p[0];
                if (kb + kk + 1 < kend) v.y = p[1];
                if (kb + kk + 2 < kend) v.z = p[2];
            }
            out[i] = v;
        }
    };
    auto sttile = [&](float (*S)[128], const float4* v) {
#pragma unroll
        for (int i = 0; i < 2; i++) {
            int fid = tid * 2 + i;
            int r = fid >> 2, kk = (fid & 3) << 2;
            S[kk + 0][r] = v[i].x; S[kk + 1][r] = v[i].y;
            S[kk + 2][r] = v[i].z; S[kk + 3][r] = v[i].w;
        }
    };

    float4 pa[2], pb[2];
    ldtile(A, m0, k0, pa);
    ldtile(B, n0, k0, pb);
    sttile(As[0], pa);
    sttile(Bs[0], pb);
    __syncthreads();

    for (int kt = 0; kt < ntiles; kt++) {
        const int cur = kt & 1;
        if (kt + 1 < ntiles) {
            ldtile(A, m0, k0 + (kt + 1) * 16, pa);
            ldtile(B, n0, k0 + (kt + 1) * 16, pb);
        }
        const float (*Ac)[128] = As[cur];
        const float (*Bc)[128] = Bs[cur];
#pragma unroll
        for (int k = 0; k < 16; k++) {
            float4 a0 = *(const float4*)&Ac[k][rowg];
            float4 a1 = *(const float4*)&Ac[k][rowg + 4];
            float4 b0 = *(const float4*)&Bc[k][colg];
            float4 b1 = *(const float4*)&Bc[k][colg + 4];
            float a[8]  = {a0.x, a0.y, a0.z, a0.w, a1.x, a1.y, a1.z, a1.w};
            float bb[8] = {b0.x, b0.y, b0.z, b0.w, b1.x, b1.y, b1.z, b1.w};
#pragma unroll
            for (int i = 0; i < 8; i++)
#pragma unroll
                for (int j = 0; j < 8; j++)
                    acc[i][j] += a[i] * bb[j];
        }
        if (kt + 1 < ntiles) {
            sttile(As[1 - cur], pa);
            sttile(Bs[1 - cur], pb);
        }
        __syncthreads();
    }

#pragma unroll
    for (int i = 0; i < 8; i++) {
        const int m = m0 + rowg + i;
        float* cp = C + (size_t)m * N + n0 + colg;
#pragma unroll
        for (int j = 0; j < 8; j++) cp[j] = acc[i][j];
    }
}

// ---------------- sum split partials + fold biases (exactly SEQ*G4/4 float4 threads) ----------------
__global__ void reduce_splits(const float* __restrict__ bufs, float* __restrict__ C,
                              const float* __restrict__ b1, const float* __restrict__ b2,
                              int s, int N)
{
    int idx = blockIdx.x * blockDim.x + threadIdx.x;
    size_t base = (size_t)idx * 4;
    float4 acc = *(const float4*)(bufs + base);
    for (int i = 1; i < s; i++) {
        float4 v = *(const float4*)(bufs + (size_t)i * ((size_t)SEQ * G4) + base);
        acc.x += v.x; acc.y += v.y; acc.z += v.z; acc.w += v.w;
    }
    int n = (int)(base % (size_t)N);
    float4 u1 = *(const float4*)(b1 + n);
    float4 u2 = *(const float4*)(b2 + n);
    acc.x += u1.x + u2.x; acc.y += u1.y + u2.y;
    acc.z += u1.z + u2.z; acc.w += u1.w + u2.w;
    *(float4*)(C + base) = acc;
}

// ---------------- generic fp32 NT GEMM (GCN path, small N) ----------------
__global__ __launch_bounds__(256) void sgemm_nt(
    const float* __restrict__ A, const float* __restrict__ B,
    float* __restrict__ C, int M, int N, int K)
{
    __shared__ float As[16][128];
    __shared__ float Bs[16][64];
    const int tx = threadIdx.x, ty = threadIdx.y;
    const int tid = ty * 16 + tx;
    const int m0 = blockIdx.y * 128, n0 = blockIdx.x * 64;

    float acc[8][4];
#pragma unroll
    for (int i = 0; i < 8; i++)
#pragma unroll
        for (int j = 0; j < 4; j++) acc[i][j] = 0.f;

    const bool k4ok = ((K & 3) == 0);
    const int ntiles = (K + 15) >> 4;

    for (int kt = 0; kt < ntiles; kt++) {
        const int kb = kt * 16;
#pragma unroll
        for (int i = 0; i < 2; i++) {
            int fid = tid * 2 + i;
            int r = fid >> 2;
            int kk = (fid & 3) << 2;
            float4 v = make_float4(0.f, 0.f, 0.f, 0.f);
            if (m0 + r < M) {
                const float* ap = A + (size_t)(m0 + r) * K + kb + kk;
                if (k4ok && kb + kk + 3 < K) v = *(const float4*)ap;
                else {
                    if (kb + kk + 0 < K) v.x = ap[0];
                    if (kb + kk + 1 < K) v.y = ap[1];
                    if (kb + kk + 2 < K) v.z = ap[2];
                    if (kb + kk + 3 < K) v.w = ap[3];
                }
            }
            As[kk + 0][r] = v.x; As[kk + 1][r] = v.y;
            As[kk + 2][r] = v.z; As[kk + 3][r] = v.w;
        }
        {
            int r = tid >> 2;
            int kk = (tid & 3) << 2;
            float4 v = make_float4(0.f, 0.f, 0.f, 0.f);
            if (n0 + r < N) {
                const float* bp = B + (size_t)(n0 + r) * K + kb + kk;
                if (k4ok && kb + kk + 3 < K) v = *(const float4*)bp;
                else {
                    if (kb + kk + 0 < K) v.x = bp[0];
                    if (kb + kk + 1 < K) v.y = bp[1];
                    if (kb + kk + 2 < K) v.z = bp[2];
                    if (kb + kk + 3 < K) v.w = bp[3];
                }
            }
            Bs[kk + 0][r] = v.x; Bs[kk + 1][r] = v.y;
            Bs[kk + 2][r] = v.z; Bs[kk + 3][r] = v.w;
        }
        __syncthreads();
#pragma unroll
        for (int k = 0; k < 16; k++) {
            float4 b4 = *(const float4*)&Bs[k][tx * 4];
            float4 a0 = *(const float4*)&As[k][ty * 8];
            float4 a1 = *(const float4*)&As[k][ty * 8 + 4];
            float a[8] = {a0.x, a0.y, a0.z, a0.w, a1.x, a1.y, a1.z, a1.w};
            float bb[4] = {b4.x, b4.y, b4.z, b4.w};
#pragma unroll
            for (int i = 0; i < 8; i++)
#pragma unroll
                for (int j = 0; j < 4; j++)
                    acc[i][j] += a[i] * bb[j];
        }
        __syncthreads();
    }
#pragma unroll
    for (int i = 0; i < 8; i++) {
        int m = m0 + ty * 8 + i;
        if (m >= M) continue;
#pragma unroll
        for (int j = 0; j < 4; j++) {
            int n = n0 + tx * 4 + j;
            if (n < N) C[(size_t)m * N + n] = acc[i][j];
        }
    }
}

// ---------------- counter reset ----------------
__global__ void zero_cnt() {
    int i = blockIdx.x * blockDim.x + threadIdx.x;
    if (i < SEQ) g_cnt[i] = 0u;
}

// ---------------- persistent LSTM recurrence (R5 topology: per-timestep counter) ----------------
// 128 CTAs x 640 threads. CTA k owns hidden units [5k,5k+5); warp w: unit u=w>>2,
// gate g=w&3, Whh row in registers. Publish: after h(t) stored, one thread per CTA does
// red.release.gpu.add(cnt[t],1). Consumers at t+1: single thread spins with ld.relaxed.gpu
// until cnt[t]==128, then ONE fence.acq_rel.gpu (acquire cost paid once, not per poll).
__global__ __launch_bounds__(640, 1) void lstm_rec(
    const float* __restrict__ xW,   // [1024, 2560] (biases folded in)
    const float* __restrict__ Whh,  // [2560, 640]
    float* __restrict__ seq_out)    // [1024, 640]
{
    __shared__ float h_s[640];
    __shared__ float dots[5][4];
    __shared__ float c_s[5];

    const int tid = threadIdx.x;
    const int w = tid >> 5, l = tid & 31;
    const int k = blockIdx.x;
    const int u = w >> 2;
    const int gsel = w & 3;
    const int uglob = 5 * k + u;
    const int row = gsel * 640 + uglob;

    float wreg[20];
    const float* wp = Whh + (size_t)row * 640 + 20 * l;
#pragma unroll
    for (int i = 0; i < 20; i++) wreg[i] = wp[i];
    if (tid < 5) c_s[tid] = 0.f;
    unsigned* cnt = g_cnt;
    __syncthreads();

    for (int t = 0; t < SEQ; t++) {
        // gate threads prefetch xW operands before the wait (off critical path)
        float xg0 = 0.f, xg1 = 0.f, xg2 = 0.f, xg3 = 0.f;
        if (tid < 5) {
            const float* xwt = xW + (size_t)t * G4 + 5 * k + tid;
            xg0 = __ldg(xwt);
            xg1 = __ldg(xwt + 640);
            xg2 = __ldg(xwt + 1280);
            xg3 = __ldg(xwt + 1920);
        }

        float acc = 0.f;
        if (t > 0) {
            if (tid == 0) {
                unsigned v;
                do {
                    asm volatile("ld.relaxed.gpu.global.u32 %0, [%1];"
                                 : "=r"(v) : "l"(cnt + (t - 1)) : "memory");
                } while (v < 128u);
                asm volatile("fence.acq_rel.gpu;" ::: "memory");
            }
            __syncthreads();
            h_s[tid] = __ldcg(seq_out + (size_t)(t - 1) * 640 + tid);
            __syncthreads();
            const float4* hp = (const float4*)(h_s + 20 * l);
#pragma unroll
            for (int i = 0; i < 5; i++) {
                float4 v = hp[i];
                acc += wreg[4 * i + 0] * v.x + wreg[4 * i + 1] * v.y
                     + wreg[4 * i + 2] * v.z + wreg[4 * i + 3] * v.w;
            }
        }
#pragma unroll
        for (int off = 16; off > 0; off >>= 1)
            acc += __shfl_down_sync(0xffffffffu, acc, off);
        if (l == 0) dots[u][gsel] = acc;
        __syncthreads();

        if (tid < 5) {
            const int uu = tid;
            const int ug = 5 * k + uu;
            float gi = xg0 + dots[uu][0];
            float gf = xg1 + dots[uu][1];
            float gg = xg2 + dots[uu][2];
            float go = xg3 + dots[uu][3];
            float iv = 1.f / (1.f + __expf(-gi));
            float fv = 1.f / (1.f + __expf(-gf));
            float gv = tanhf(gg);
            float ov = 1.f / (1.f + __expf(-go));
            float c = fv * c_s[uu] + iv * gv;
            c_s[uu] = c;
            seq_out[(size_t)t * 640 + ug] = ov * tanhf(c);
        }
        __syncthreads();   // order gate-thread stores before the release
        if (tid == 0) {
            asm volatile("red.release.gpu.global.add.u32 [%0], %1;"
                         :: "l"(cnt + t), "r"(1u) : "memory");
        }
    }
}

// ---------------- graph prep ----------------
__global__ void zero_deg(int* deg) {
    int i = blockIdx.x * blockDim.x + threadIdx.x;
    if (i < NNODES) deg[i] = 0;
}
__global__ void count_deg(const int* __restrict__ dst, int* deg) {
    int e = blockIdx.x * blockDim.x + threadIdx.x;
    if (e < NEDGES) atomicAdd(&deg[dst[e]], 1);
}
__global__ void finalize_deg(const int* __restrict__ deg, float* dinv, float* selfnorm) {
    int i = blockIdx.x * blockDim.x + threadIdx.x;
    if (i < NNODES) {
        float d = rsqrtf((float)(deg[i] + 1));
        dinv[i] = d;
        selfnorm[i] = d * d;
    }
}
__global__ void edge_norm(const int* __restrict__ src, const int* __restrict__ dst,
                          const float* __restrict__ dinv, float* enorm) {
    int e = blockIdx.x * blockDim.x + threadIdx.x;
    if (e < NEDGES) enorm[e] = dinv[src[e]] * dinv[dst[e]];
}
__global__ void transpose_k(const float* __restrict__ W, float* __restrict__ Wt,
                            int Cin, int Cout) {
    int idx = blockIdx.x * blockDim.x + threadIdx.x;
    if (idx < Cin * Cout) {
        int i = idx / Cout, o = idx % Cout;
        Wt[o * Cin + i] = W[idx];
    }
}

// ---------------- GCN scatter ----------------
__global__ void scatter_init(const float* __restrict__ h, const float* __restrict__ selfnorm,
                             float* __restrict__ y, int C) {
    int idx = blockIdx.x * blockDim.x + threadIdx.x;
    if (idx < NNODES * C) {
        int i = idx / C;
        y[idx] = selfnorm[i] * h[idx];
    }
}
__global__ void scatter_edges(const float* __restrict__ h, const float* __restrict__ enorm,
                              const int* __restrict__ src, const int* __restrict__ dst,
                              float* __restrict__ y, int C) {
    int idx = blockIdx.x * blockDim.x + threadIdx.x;
    if (idx < NEDGES * C) {
        int e = idx / C, c = idx - e * C;
        atomicAdd(&y[dst[e] * C + c], enorm[e] * h[src[e] * C + c]);
    }
}

// ---------------- bias + leaky + batchnorm (per-column CTA) ----------------
__global__ void bias_leaky_bn(const float* __restrict__ y, const float* __restrict__ b,
                              float* __restrict__ out, int C) {
    const int c = blockIdx.x;
    const int tid = threadIdx.x;
    const float bias = b[c];
    float s = 0.f, sq = 0.f;
    for (int r = tid; r < NNODES; r += 256) {
        float v = y[r * C + c] + bias;
        v = (v > 0.f) ? v : 0.01f * v;
        s += v; sq += v * v;
    }
    __shared__ float rs[256], rq[256];
    rs[tid] = s; rq[tid] = sq;
    __syncthreads();
    for (int o = 128; o > 0; o >>= 1) {
        if (tid < o) { rs[tid] += rs[tid + o]; rq[tid] += rq[tid + o]; }
        __syncthreads();
    }
    float mean = rs[0] * (1.f / NNODES);
    float var = rq[0] * (1.f / NNODES) - mean * mean;
    float rstd = rsqrtf(var + 1e-5f);
    for (int r = tid; r < NNODES; r += 256) {
        float v = y[r * C + c] + bias;
        v = (v > 0.f) ? v : 0.01f * v;
        out[r * C + c] = (v - mean) * rstd;
    }
}

// ---------------- head: segment sum + concat + 3 FC ----------------
__global__ void head_kernel(const float* __restrict__ x,
                            const float* __restrict__ gender, const float* __restrict__ handed,
                            const float* __restrict__ W1, const float* __restrict__ b1,
                            const float* __restrict__ W2, const float* __restrict__ b2,
                            const float* __restrict__ W3, const float* __restrict__ b3,
                            float* __restrict__ out) {
    const int b = blockIdx.x;
    const int tid = threadIdx.x;
    __shared__ float feat[52];
    __shared__ float y1[32], y2[16];
    if (tid < 50) {
        float s = 0.f;
        for (int r = 0; r < 64; r++) s += x[(b * 64 + r) * 50 + tid];
        feat[tid] = s;
    }
    if (tid == 50) feat[50] = gender[b];
    if (tid == 51) feat[51] = handed[b];
    __syncthreads();
    if (tid < 32) {
        float s = b1[tid];
        for (int i = 0; i < 52; i++) s += feat[i] * W1[tid * 52 + i];
        y1[tid] = s;
    }
    __syncthreads();
    if (tid < 16) {
        float s = b2[tid];
        for (int i = 0; i < 32; i++) s += y1[i] * W2[tid * 32 + i];
        y2[tid] = s;
    }
    __syncthreads();
    if (tid == 0) {
        float s = b3[0];
        for (int i = 0; i < 16; i++) s += y2[i] * W3[i];
        out[b] = s;
    }
}

// ---------------- host ----------------
extern "C" void kernel_launch(void* const* d_in, const int* in_sizes, int n_in,
                              void* d_out, int out_size) {
    const float* x_in   = (const float*)d_in[0];
    const int*   eidx   = (const int*)d_in[1];
    const float* gender = (const float*)d_in[2];
    const float* handed = (const float*)d_in[3];
    const float* Wih[3] = {(const float*)d_in[4], (const float*)d_in[8],  (const float*)d_in[12]};
    const float* Whh[3] = {(const float*)d_in[5], (const float*)d_in[9],  (const float*)d_in[13]};
    const float* bih[3] = {(const float*)d_in[6], (const float*)d_in[10], (const float*)d_in[14]};
    const float* bhh[3] = {(const float*)d_in[7], (const float*)d_in[11], (const float*)d_in[15]};
    const float* gcnW[4] = {(const float*)d_in[16], (const float*)d_in[18], (const float*)d_in[20], (const float*)d_in[22]};
    const float* gcnB[4] = {(const float*)d_in[17], (const float*)d_in[19], (const float*)d_in[21], (const float*)d_in[23]};
    const float* fcW[3] = {(const float*)d_in[24], (const float*)d_in[26], (const float*)d_in[28]};
    const float* fcB[3] = {(const float*)d_in[25], (const float*)d_in[27], (const float*)d_in[29]};

    float *xWp, *xW, *bufA, *bufB, *gh, *gy, *Wt, *dinv, *selfnorm, *enorm;
    int* deg;
    cudaGetSymbolAddress((void**)&xWp, g_xWp);
    cudaGetSymbolAddress((void**)&xW, g_xW);
    cudaGetSymbolAddress((void**)&bufA, g_bufA);
    cudaGetSymbolAddress((void**)&bufB, g_bufB);
    cudaGetSymbolAddress((void**)&gh, g_gh);
    cudaGetSymbolAddress((void**)&gy, g_gy);
    cudaGetSymbolAddress((void**)&Wt, g_Wt);
    cudaGetSymbolAddress((void**)&deg, g_deg);
    cudaGetSymbolAddress((void**)&dinv, g_dinv);
    cudaGetSymbolAddress((void**)&selfnorm, g_selfnorm);
    cudaGetSymbolAddress((void**)&enorm, g_enorm);

    const int* src = eidx;
    const int* dst = eidx + NEDGES;
    dim3 tb(16, 16);
    const int nred = (SEQ * G4) / 4 / 256;   // 2560 CTAs, exact

    // ---- LSTM layer 0 (K=8500, split-K s=8, Kc=1064 multiple of 4) ----
    sgemm128_split<<<dim3(G4 / 128, SEQ / 128, 8), 256>>>(x_in, Wih[0], xWp, SEQ, G4, 8500, 1064);
    reduce_splits<<<nred, 256>>>(xWp, xW, bih[0], bhh[0], 8, G4);
    zero_cnt<<<4, 256>>>();
    lstm_rec<<<NCTA_REC, 640>>>(xW, Whh[0], bufA);

    // ---- LSTM layer 1 (K=640, split-K s=2) ----
    sgemm128_split<<<dim3(G4 / 128, SEQ / 128, 2), 256>>>(bufA, Wih[1], xWp, SEQ, G4, HDIM, 320);
    reduce_splits<<<nred, 256>>>(xWp, xW, bih[1], bhh[1], 2, G4);
    zero_cnt<<<4, 256>>>();
    lstm_rec<<<NCTA_REC, 640>>>(xW, Whh[1], bufB);

    // ---- LSTM layer 2 ----
    sgemm128_split<<<dim3(G4 / 128, SEQ / 128, 2), 256>>>(bufB, Wih[2], xWp, SEQ, G4, HDIM, 320);
    reduce_splits<<<nred, 256>>>(xWp, xW, bih[2], bhh[2], 2, G4);
    zero_cnt<<<4, 256>>>();
    lstm_rec<<<NCTA_REC, 640>>>(xW, Whh[2], bufA);

    // ---- graph prep ----
    zero_deg<<<4, 256>>>(deg);
    count_deg<<<NEDGES / 256, 256>>>(dst, deg);
    finalize_deg<<<4, 256>>>(deg, dinv, selfnorm);
    edge_norm<<<NEDGES / 256, 256>>>(src, dst, dinv, enorm);

    // ---- GCN layers ----
    const int cins[4]  = {640, 320, 180, 90};
    const int couts[4] = {320, 180, 90, 50};
    float* xcur = bufA;
    float* xnext = bufB;
    for (int l = 0; l < 4; l++) {
        int Cin = cins[l], Cout = couts[l];
        transpose_k<<<(Cin * Cout + 255) / 256, 256>>>(gcnW[l], Wt, Cin, Cout);
        sgemm_nt<<<dim3((Cout + 63) / 64, NNODES / 128), tb>>>(xcur, Wt, gh, NNODES, Cout, Cin);
        scatter_init<<<(NNODES * Cout + 255) / 256, 256>>>(gh, selfnorm, gy, Cout);
        scatter_edges<<<(NEDGES * Cout + 255) / 256, 256>>>(gh, enorm, src, dst, gy, Cout);
        bias_leaky_bn<<<Cout, 256>>>(gy, gcnB[l], xnext, Cout);
        float* tmp = xcur; xcur = xnext; xnext = tmp;
    }

    // ---- head ----
    head_kernel<<<BSZ, 64>>>(xcur, gender, handed,
                             fcW[0], fcB[0], fcW[1], fcB[1], fcW[2], fcB[2],
                             (float*)d_out);
}

// round 8
// speedup vs baseline: 1.7592x; 1.0711x over previous
#include <cuda_runtime.h>

#define SEQ     1024
#define HDIM    640
#define G4      2560
#define NNODES  1024
#define NEDGES  16384
#define BSZ     16
#define NCTA_REC 128
#define MAXSPLIT 8

// ---------------- scratch (device globals; no runtime allocation) ----------------
__device__ float g_xWp[MAXSPLIT][SEQ * G4]; // 84 MB  split-K partials
__device__ float g_xW[SEQ * G4];            // 10.5 MB reduced LSTM input projections
__device__ float g_bufA[SEQ * HDIM];
__device__ float g_bufB[SEQ * HDIM];
__device__ float g_gh[NNODES * 320];
__device__ float g_gy[NNODES * 320];
__device__ float g_Wt[640 * 320];
__device__ int   g_deg[NNODES];
__device__ float g_dinv[NNODES];
__device__ float g_selfnorm[NNODES];
__device__ float g_enorm[NEDGES];
__device__ unsigned g_cnt[SEQ];             // per-timestep publish counters

__device__ __forceinline__ float fsigmoid(float x) { return 1.f / (1.f + __expf(-x)); }
__device__ __forceinline__ float ftanh(float x) { return 2.f / (1.f + __expf(-2.f * x)) - 1.f; }

// ---------------- split-K fp32 NT GEMM: partial C_z = A[:,kz]*B[:,kz]^T ----------------
// BM=128 BN=128 BK=16, 256 threads, 8x8/thread, double-buffered. M%128==0, N%128==0.
__global__ __launch_bounds__(256) void sgemm128_split(
    const float* __restrict__ A, const float* __restrict__ B,
    float* __restrict__ Cbase, int M, int N, int K, int Kc)
{
    __shared__ float As[2][16][128];
    __shared__ float Bs[2][16][128];
    const int tid = threadIdx.x;
    const int z = blockIdx.z;
    const int k0 = z * Kc;
    const int kend = min(K, k0 + Kc);
    float* __restrict__ C = Cbase + (size_t)z * ((size_t)SEQ * G4);
    const int m0 = blockIdx.y * 128, n0 = blockIdx.x * 128;
    const int rowg = (tid >> 4) << 3;
    const int colg = (tid & 15) << 3;

    float acc[8][8];
#pragma unroll
    for (int i = 0; i < 8; i++)
#pragma unroll
        for (int j = 0; j < 8; j++) acc[i][j] = 0.f;

    const int ntiles = (kend - k0 + 15) >> 4;

    auto ldtile = [&](const float* __restrict__ P, int base_row, int kb, float4* out) {
#pragma unroll
        for (int i = 0; i < 2; i++) {
            int fid = tid * 2 + i;
            int r = fid >> 2, kk = (fid & 3) << 2;
            float4 v = make_float4(0.f, 0.f, 0.f, 0.f);
            const float* p = P + (size_t)(base_row + r) * K + kb + kk;
            if (kb + kk + 3 < kend) v = *(const float4*)p;
            else {
                if (kb + kk + 0 < kend) v.x = p[0];
                if (kb + kk + 1 < kend) v.y = p[1];
                if (kb + kk + 2 < kend) v.z = p[2];
            }
            out[i] = v;
        }
    };
    auto sttile = [&](float (*S)[128], const float4* v) {
#pragma unroll
        for (int i = 0; i < 2; i++) {
            int fid = tid * 2 + i;
            int r = fid >> 2, kk = (fid & 3) << 2;
            S[kk + 0][r] = v[i].x; S[kk + 1][r] = v[i].y;
            S[kk + 2][r] = v[i].z; S[kk + 3][r] = v[i].w;
        }
    };

    float4 pa[2], pb[2];
    ldtile(A, m0, k0, pa);
    ldtile(B, n0, k0, pb);
    sttile(As[0], pa);
    sttile(Bs[0], pb);
    __syncthreads();

    for (int kt = 0; kt < ntiles; kt++) {
        const int cur = kt & 1;
        if (kt + 1 < ntiles) {
            ldtile(A, m0, k0 + (kt + 1) * 16, pa);
            ldtile(B, n0, k0 + (kt + 1) * 16, pb);
        }
        const float (*Ac)[128] = As[cur];
        const float (*Bc)[128] = Bs[cur];
#pragma unroll
        for (int k = 0; k < 16; k++) {
            float4 a0 = *(const float4*)&Ac[k][rowg];
            float4 a1 = *(const float4*)&Ac[k][rowg + 4];
            float4 b0 = *(const float4*)&Bc[k][colg];
            float4 b1 = *(const float4*)&Bc[k][colg + 4];
            float a[8]  = {a0.x, a0.y, a0.z, a0.w, a1.x, a1.y, a1.z, a1.w};
            float bb[8] = {b0.x, b0.y, b0.z, b0.w, b1.x, b1.y, b1.z, b1.w};
#pragma unroll
            for (int i = 0; i < 8; i++)
#pragma unroll
                for (int j = 0; j < 8; j++)
                    acc[i][j] += a[i] * bb[j];
        }
        if (kt + 1 < ntiles) {
            sttile(As[1 - cur], pa);
            sttile(Bs[1 - cur], pb);
        }
        __syncthreads();
    }

#pragma unroll
    for (int i = 0; i < 8; i++) {
        const int m = m0 + rowg + i;
        float* cp = C + (size_t)m * N + n0 + colg;
#pragma unroll
        for (int j = 0; j < 8; j++) cp[j] = acc[i][j];
    }
}

// ---------------- sum split partials + fold biases ----------------
__global__ void reduce_splits(const float* __restrict__ bufs, float* __restrict__ C,
                              const float* __restrict__ b1, const float* __restrict__ b2,
                              int s, int N)
{
    int idx = blockIdx.x * blockDim.x + threadIdx.x;
    size_t base = (size_t)idx * 4;
    float4 acc = *(const float4*)(bufs + base);
    for (int i = 1; i < s; i++) {
        float4 v = *(const float4*)(bufs + (size_t)i * ((size_t)SEQ * G4) + base);
        acc.x += v.x; acc.y += v.y; acc.z += v.z; acc.w += v.w;
    }
    int n = (int)(base % (size_t)N);
    float4 u1 = *(const float4*)(b1 + n);
    float4 u2 = *(const float4*)(b2 + n);
    acc.x += u1.x + u2.x; acc.y += u1.y + u2.y;
    acc.z += u1.z + u2.z; acc.w += u1.w + u2.w;
    *(float4*)(C + base) = acc;
}

// ---------------- generic fp32 NT GEMM (GCN path, small N) ----------------
__global__ __launch_bounds__(256) void sgemm_nt(
    const float* __restrict__ A, const float* __restrict__ B,
    float* __restrict__ C, int M, int N, int K)
{
    __shared__ float As[16][128];
    __shared__ float Bs[16][64];
    const int tx = threadIdx.x, ty = threadIdx.y;
    const int tid = ty * 16 + tx;
    const int m0 = blockIdx.y * 128, n0 = blockIdx.x * 64;

    float acc[8][4];
#pragma unroll
    for (int i = 0; i < 8; i++)
#pragma unroll
        for (int j = 0; j < 4; j++) acc[i][j] = 0.f;

    const bool k4ok = ((K & 3) == 0);
    const int ntiles = (K + 15) >> 4;

    for (int kt = 0; kt < ntiles; kt++) {
        const int kb = kt * 16;
#pragma unroll
        for (int i = 0; i < 2; i++) {
            int fid = tid * 2 + i;
            int r = fid >> 2;
            int kk = (fid & 3) << 2;
            float4 v = make_float4(0.f, 0.f, 0.f, 0.f);
            if (m0 + r < M) {
                const float* ap = A + (size_t)(m0 + r) * K + kb + kk;
                if (k4ok && kb + kk + 3 < K) v = *(const float4*)ap;
                else {
                    if (kb + kk + 0 < K) v.x = ap[0];
                    if (kb + kk + 1 < K) v.y = ap[1];
                    if (kb + kk + 2 < K) v.z = ap[2];
                    if (kb + kk + 3 < K) v.w = ap[3];
                }
            }
            As[kk + 0][r] = v.x; As[kk + 1][r] = v.y;
            As[kk + 2][r] = v.z; As[kk + 3][r] = v.w;
        }
        {
            int r = tid >> 2;
            int kk = (tid & 3) << 2;
            float4 v = make_float4(0.f, 0.f, 0.f, 0.f);
            if (n0 + r < N) {
                const float* bp = B + (size_t)(n0 + r) * K + kb + kk;
                if (k4ok && kb + kk + 3 < K) v = *(const float4*)bp;
                else {
                    if (kb + kk + 0 < K) v.x = bp[0];
                    if (kb + kk + 1 < K) v.y = bp[1];
                    if (kb + kk + 2 < K) v.z = bp[2];
                    if (kb + kk + 3 < K) v.w = bp[3];
                }
            }
            Bs[kk + 0][r] = v.x; Bs[kk + 1][r] = v.y;
            Bs[kk + 2][r] = v.z; Bs[kk + 3][r] = v.w;
        }
        __syncthreads();
#pragma unroll
        for (int k = 0; k < 16; k++) {
            float4 b4 = *(const float4*)&Bs[k][tx * 4];
            float4 a0 = *(const float4*)&As[k][ty * 8];
            float4 a1 = *(const float4*)&As[k][ty * 8 + 4];
            float a[8] = {a0.x, a0.y, a0.z, a0.w, a1.x, a1.y, a1.z, a1.w};
            float bb[4] = {b4.x, b4.y, b4.z, b4.w};
#pragma unroll
            for (int i = 0; i < 8; i++)
#pragma unroll
                for (int j = 0; j < 4; j++)
                    acc[i][j] += a[i] * bb[j];
        }
        __syncthreads();
    }
#pragma unroll
    for (int i = 0; i < 8; i++) {
        int m = m0 + ty * 8 + i;
        if (m >= M) continue;
#pragma unroll
        for (int j = 0; j < 4; j++) {
            int n = n0 + tx * 4 + j;
            if (n < N) C[(size_t)m * N + n] = acc[i][j];
        }
    }
}

// ---------------- counter reset ----------------
__global__ void zero_cnt() {
    int i = blockIdx.x * blockDim.x + threadIdx.x;
    if (i < SEQ) g_cnt[i] = 0u;
}

// ---------------- persistent LSTM recurrence (R5 topology, warp0-only tail) ----------------
// 128 CTAs x 640 threads. CTA k owns hidden units [5k,5k+5); warp w: unit u=w>>2,
// gate g=w&3, Whh row in registers. Publish: red.release.gpu.add(cnt[t],1) from lane 0
// of warp 0 after a __syncwarp (gate stores are lanes 0-4 of warp 0 -> warp-local
// ordering + release store suffices; NO CTA-wide trailing barrier). Consumers spin with
// ld.acquire.gpu (strong LDG, no MEMBAR) until cnt[t-1]==128.
__global__ __launch_bounds__(640, 1) void lstm_rec(
    const float* __restrict__ xW,   // [1024, 2560] (biases folded in)
    const float* __restrict__ Whh,  // [2560, 640]
    float* __restrict__ seq_out)    // [1024, 640]
{
    __shared__ float h_s[640];
    __shared__ float dots[5][4];
    __shared__ float c_s[5];

    const int tid = threadIdx.x;
    const int w = tid >> 5, l = tid & 31;
    const int k = blockIdx.x;
    const int u = w >> 2;
    const int gsel = w & 3;
    const int uglob = 5 * k + u;
    const int row = gsel * 640 + uglob;

    float wreg[20];
    const float* wp = Whh + (size_t)row * 640 + 20 * l;
#pragma unroll
    for (int i = 0; i < 20; i++) wreg[i] = wp[i];
    if (tid < 5) c_s[tid] = 0.f;
    unsigned* cnt = g_cnt;
    __syncthreads();

    for (int t = 0; t < SEQ; t++) {
        // warp-0 gate lanes prefetch xW operands before the wait (off critical path)
        float xg0 = 0.f, xg1 = 0.f, xg2 = 0.f, xg3 = 0.f;
        if (tid < 5) {
            const float* xwt = xW + (size_t)t * G4 + 5 * k + tid;
            xg0 = __ldg(xwt);
            xg1 = __ldg(xwt + 640);
            xg2 = __ldg(xwt + 1280);
            xg3 = __ldg(xwt + 1920);
        }

        float acc = 0.f;
        if (t > 0) {
            if (tid == 0) {
                unsigned v;
                do {
                    asm volatile("ld.acquire.gpu.global.u32 %0, [%1];"
                                 : "=r"(v) : "l"(cnt + (t - 1)) : "memory");
                } while (v < 128u);
            }
            __syncthreads();
            h_s[tid] = __ldcg(seq_out + (size_t)(t - 1) * 640 + tid);
            __syncthreads();
            const float4* hp = (const float4*)(h_s + 20 * l);
#pragma unroll
            for (int i = 0; i < 5; i++) {
                float4 v = hp[i];
                acc += wreg[4 * i + 0] * v.x + wreg[4 * i + 1] * v.y
                     + wreg[4 * i + 2] * v.z + wreg[4 * i + 3] * v.w;
            }
        }
#pragma unroll
        for (int off = 16; off > 0; off >>= 1)
            acc += __shfl_down_sync(0xffffffffu, acc, off);
        if (l == 0) dots[u][gsel] = acc;
        __syncthreads();

        if (w == 0) {
            if (l < 5) {
                const int uu = l;
                const int ug = 5 * k + uu;
                float gi = xg0 + dots[uu][0];
                float gf = xg1 + dots[uu][1];
                float gg = xg2 + dots[uu][2];
                float go = xg3 + dots[uu][3];
                float iv = fsigmoid(gi);
                float fv = fsigmoid(gf);
                float gv = ftanh(gg);
                float ov = fsigmoid(go);
                float c = fv * c_s[uu] + iv * gv;
                c_s[uu] = c;
                seq_out[(size_t)t * 640 + ug] = ov * ftanh(c);
            }
            __syncwarp(0xffffffffu);
            if (l == 0) {
                asm volatile("red.release.gpu.global.add.u32 [%0], %1;"
                             :: "l"(cnt + t), "r"(1u) : "memory");
            }
        }
        // non-gate warps park at the next iteration's post-poll __syncthreads;
        // h_s/dots rewrites at t+1 occur only after warp 0 passes that barrier.
    }
}

// ---------------- graph prep ----------------
__global__ void zero_deg(int* deg) {
    int i = blockIdx.x * blockDim.x + threadIdx.x;
    if (i < NNODES) deg[i] = 0;
}
__global__ void count_deg(const int* __restrict__ dst, int* deg) {
    int e = blockIdx.x * blockDim.x + threadIdx.x;
    if (e < NEDGES) atomicAdd(&deg[dst[e]], 1);
}
__global__ void finalize_deg(const int* __restrict__ deg, float* dinv, float* selfnorm) {
    int i = blockIdx.x * blockDim.x + threadIdx.x;
    if (i < NNODES) {
        float d = rsqrtf((float)(deg[i] + 1));
        dinv[i] = d;
        selfnorm[i] = d * d;
    }
}
__global__ void edge_norm(const int* __restrict__ src, const int* __restrict__ dst,
                          const float* __restrict__ dinv, float* enorm) {
    int e = blockIdx.x * blockDim.x + threadIdx.x;
    if (e < NEDGES) enorm[e] = dinv[src[e]] * dinv[dst[e]];
}
__global__ void transpose_k(const float* __restrict__ W, float* __restrict__ Wt,
                            int Cin, int Cout) {
    int idx = blockIdx.x * blockDim.x + threadIdx.x;
    if (idx < Cin * Cout) {
        int i = idx / Cout, o = idx % Cout;
        Wt[o * Cin + i] = W[idx];
    }
}

// ---------------- GCN scatter ----------------
__global__ void scatter_init(const float* __restrict__ h, const float* __restrict__ selfnorm,
                             float* __restrict__ y, int C) {
    int idx = blockIdx.x * blockDim.x + threadIdx.x;
    if (idx < NNODES * C) {
        int i = idx / C;
        y[idx] = selfnorm[i] * h[idx];
    }
}
__global__ void scatter_edges(const float* __restrict__ h, const float* __restrict__ enorm,
                              const int* __restrict__ src, const int* __restrict__ dst,
                              float* __restrict__ y, int C) {
    int idx = blockIdx.x * blockDim.x + threadIdx.x;
    if (idx < NEDGES * C) {
        int e = idx / C, c = idx - e * C;
        atomicAdd(&y[dst[e] * C + c], enorm[e] * h[src[e] * C + c]);
    }
}

// ---------------- bias + leaky + batchnorm (per-column CTA) ----------------
__global__ void bias_leaky_bn(const float* __restrict__ y, const float* __restrict__ b,
                              float* __restrict__ out, int C) {
    const int c = blockIdx.x;
    const int tid = threadIdx.x;
    const float bias = b[c];
    float s = 0.f, sq = 0.f;
    for (int r = tid; r < NNODES; r += 256) {
        float v = y[r * C + c] + bias;
        v = (v > 0.f) ? v : 0.01f * v;
        s += v; sq += v * v;
    }
    __shared__ float rs[256], rq[256];
    rs[tid] = s; rq[tid] = sq;
    __syncthreads();
    for (int o = 128; o > 0; o >>= 1) {
        if (tid < o) { rs[tid] += rs[tid + o]; rq[tid] += rq[tid + o]; }
        __syncthreads();
    }
    float mean = rs[0] * (1.f / NNODES);
    float var = rq[0] * (1.f / NNODES) - mean * mean;
    float rstd = rsqrtf(var + 1e-5f);
    for (int r = tid; r < NNODES; r += 256) {
        float v = y[r * C + c] + bias;
        v = (v > 0.f) ? v : 0.01f * v;
        out[r * C + c] = (v - mean) * rstd;
    }
}

// ---------------- head: segment sum + concat + 3 FC ----------------
__global__ void head_kernel(const float* __restrict__ x,
                            const float* __restrict__ gender, const float* __restrict__ handed,
                            const float* __restrict__ W1, const float* __restrict__ b1,
                            const float* __restrict__ W2, const float* __restrict__ b2,
                            const float* __restrict__ W3, const float* __restrict__ b3,
                            float* __restrict__ out) {
    const int b = blockIdx.x;
    const int tid = threadIdx.x;
    __shared__ float feat[52];
    __shared__ float y1[32], y2[16];
    if (tid < 50) {
        float s = 0.f;
        for (int r = 0; r < 64; r++) s += x[(b * 64 + r) * 50 + tid];
        feat[tid] = s;
    }
    if (tid == 50) feat[50] = gender[b];
    if (tid == 51) feat[51] = handed[b];
    __syncthreads();
    if (tid < 32) {
        float s = b1[tid];
        for (int i = 0; i < 52; i++) s += feat[i] * W1[tid * 52 + i];
        y1[tid] = s;
    }
    __syncthreads();
    if (tid < 16) {
        float s = b2[tid];
        for (int i = 0; i < 32; i++) s += y1[i] * W2[tid * 32 + i];
        y2[tid] = s;
    }
    __syncthreads();
    if (tid == 0) {
        float s = b3[0];
        for (int i = 0; i < 16; i++) s += y2[i] * W3[i];
        out[b] = s;
    }
}

// ---------------- host ----------------
extern "C" void kernel_launch(void* const* d_in, const int* in_sizes, int n_in,
                              void* d_out, int out_size) {
    const float* x_in   = (const float*)d_in[0];
    const int*   eidx   = (const int*)d_in[1];
    const float* gender = (const float*)d_in[2];
    const float* handed = (const float*)d_in[3];
    const float* Wih[3] = {(const float*)d_in[4], (const float*)d_in[8],  (const float*)d_in[12]};
    const float* Whh[3] = {(const float*)d_in[5], (const float*)d_in[9],  (const float*)d_in[13]};
    const float* bih[3] = {(const float*)d_in[6], (const float*)d_in[10], (const float*)d_in[14]};
    const float* bhh[3] = {(const float*)d_in[7], (const float*)d_in[11], (const float*)d_in[15]};
    const float* gcnW[4] = {(const float*)d_in[16], (const float*)d_in[18], (const float*)d_in[20], (const float*)d_in[22]};
    const float* gcnB[4] = {(const float*)d_in[17], (const float*)d_in[19], (const float*)d_in[21], (const float*)d_in[23]};
    const float* fcW[3] = {(const float*)d_in[24], (const float*)d_in[26], (const float*)d_in[28]};
    const float* fcB[3] = {(const float*)d_in[25], (const float*)d_in[27], (const float*)d_in[29]};

    float *xWp, *xW, *bufA, *bufB, *gh, *gy, *Wt, *dinv, *selfnorm, *enorm;
    int* deg;
    cudaGetSymbolAddress((void**)&xWp, g_xWp);
    cudaGetSymbolAddress((void**)&xW, g_xW);
    cudaGetSymbolAddress((void**)&bufA, g_bufA);
    cudaGetSymbolAddress((void**)&bufB, g_bufB);
    cudaGetSymbolAddress((void**)&gh, g_gh);
    cudaGetSymbolAddress((void**)&gy, g_gy);
    cudaGetSymbolAddress((void**)&Wt, g_Wt);
    cudaGetSymbolAddress((void**)&deg, g_deg);
    cudaGetSymbolAddress((void**)&dinv, g_dinv);
    cudaGetSymbolAddress((void**)&selfnorm, g_selfnorm);
    cudaGetSymbolAddress((void**)&enorm, g_enorm);

    const int* src = eidx;
    const int* dst = eidx + NEDGES;
    dim3 tb(16, 16);
    const int nred = (SEQ * G4) / 4 / 256;   // 2560 CTAs, exact

    // ---- LSTM layer 0 (K=8500, split-K s=8, Kc=1064 multiple of 4) ----
    sgemm128_split<<<dim3(G4 / 128, SEQ / 128, 8), 256>>>(x_in, Wih[0], xWp, SEQ, G4, 8500, 1064);
    reduce_splits<<<nred, 256>>>(xWp, xW, bih[0], bhh[0], 8, G4);
    zero_cnt<<<4, 256>>>();
    lstm_rec<<<NCTA_REC, 640>>>(xW, Whh[0], bufA);

    // ---- LSTM layer 1 (K=640, split-K s=2) ----
    sgemm128_split<<<dim3(G4 / 128, SEQ / 128, 2), 256>>>(bufA, Wih[1], xWp, SEQ, G4, HDIM, 320);
    reduce_splits<<<nred, 256>>>(xWp, xW, bih[1], bhh[1], 2, G4);
    zero_cnt<<<4, 256>>>();
    lstm_rec<<<NCTA_REC, 640>>>(xW, Whh[1], bufB);

    // ---- LSTM layer 2 ----
    sgemm128_split<<<dim3(G4 / 128, SEQ / 128, 2), 256>>>(bufB, Wih[2], xWp, SEQ, G4, HDIM, 320);
    reduce_splits<<<nred, 256>>>(xWp, xW, bih[2], bhh[2], 2, G4);
    zero_cnt<<<4, 256>>>();
    lstm_rec<<<NCTA_REC, 640>>>(xW, Whh[2], bufA);

    // ---- graph prep ----
    zero_deg<<<4, 256>>>(deg);
    count_deg<<<NEDGES / 256, 256>>>(dst, deg);
    finalize_deg<<<4, 256>>>(deg, dinv, selfnorm);
    edge_norm<<<NEDGES / 256, 256>>>(src, dst, dinv, enorm);

    // ---- GCN layers ----
    const int cins[4]  = {640, 320, 180, 90};
    const int couts[4] = {320, 180, 90, 50};
    float* xcur = bufA;
    float* xnext = bufB;
    for (int l = 0; l < 4; l++) {
        int Cin = cins[l], Cout = couts[l];
        transpose_k<<<(Cin * Cout + 255) / 256, 256>>>(gcnW[l], Wt, Cin, Cout);
        sgemm_nt<<<dim3((Cout + 63) / 64, NNODES / 128), tb>>>(xcur, Wt, gh, NNODES, Cout, Cin);
        scatter_init<<<(NNODES * Cout + 255) / 256, 256>>>(gh, selfnorm, gy, Cout);
        scatter_edges<<<(NEDGES * Cout + 255) / 256, 256>>>(gh, enorm, src, dst, gy, Cout);
        bias_leaky_bn<<<Cout, 256>>>(gy, gcnB[l], xnext, Cout);
        float* tmp = xcur; xcur = xnext; xnext = tmp;
    }

    // ---- head ----
    head_kernel<<<BSZ, 64>>>(xcur, gender, handed,
                             fcW[0], fcB[0], fcW[1], fcB[1], fcW[2], fcB[2],
                             (float*)d_out);
}

// round 9
// speedup vs baseline: 1.8119x; 1.0299x over previous
#include <cuda_runtime.h>

#define SEQ     1024
#define HDIM    640
#define G4      2560
#define NNODES  1024
#define NEDGES  16384
#define BSZ     16
#define NCTA_REC 128
#define MAXSPLIT 8
#define SENTINEL_U 0x40000000u   /* 2.0f — impossible for |h|<1 */

// ---------------- scratch (device globals; no runtime allocation) ----------------
__device__ float g_xWp[MAXSPLIT][SEQ * G4]; // 84 MB  split-K partials
__device__ float g_xW[SEQ * G4];            // 10.5 MB reduced LSTM input projections
__device__ float g_bufA[SEQ * HDIM];
__device__ float g_bufB[SEQ * HDIM];
__device__ float g_gh[NNODES * 320];
__device__ float g_gy[NNODES * 320];
__device__ float g_Wt[640 * 320];
__device__ int   g_deg[NNODES];
__device__ float g_dinv[NNODES];
__device__ float g_selfnorm[NNODES];
__device__ float g_enorm[NEDGES];

__device__ __forceinline__ float fsigmoid(float x) { return 1.f / (1.f + __expf(-x)); }
__device__ __forceinline__ float ftanh(float x) { return 2.f / (1.f + __expf(-2.f * x)) - 1.f; }

// ---------------- split-K fp32 NT GEMM: partial C_z = A[:,kz]*B[:,kz]^T ----------------
// BM=128 BN=128 BK=16, 256 threads, 8x8/thread, double-buffered. M%128==0, N%128==0.
__global__ __launch_bounds__(256) void sgemm128_split(
    const float* __restrict__ A, const float* __restrict__ B,
    float* __restrict__ Cbase, int M, int N, int K, int Kc)
{
    __shared__ float As[2][16][128];
    __shared__ float Bs[2][16][128];
    const int tid = threadIdx.x;
    const int z = blockIdx.z;
    const int k0 = z * Kc;
    const int kend = min(K, k0 + Kc);
    float* __restrict__ C = Cbase + (size_t)z * ((size_t)SEQ * G4);
    const int m0 = blockIdx.y * 128, n0 = blockIdx.x * 128;
    const int rowg = (tid >> 4) << 3;
    const int colg = (tid & 15) << 3;

    float acc[8][8];
#pragma unroll
    for (int i = 0; i < 8; i++)
#pragma unroll
        for (int j = 0; j < 8; j++) acc[i][j] = 0.f;

    const int ntiles = (kend - k0 + 15) >> 4;

    auto ldtile = [&](const float* __restrict__ P, int base_row, int kb, float4* out) {
#pragma unroll
        for (int i = 0; i < 2; i++) {
            int fid = tid * 2 + i;
            int r = fid >> 2, kk = (fid & 3) << 2;
            float4 v = make_float4(0.f, 0.f, 0.f, 0.f);
            const float* p = P + (size_t)(base_row + r) * K + kb + kk;
            if (kb + kk + 3 < kend) v = *(const float4*)p;
            else {
                if (kb + kk + 0 < kend) v.x = p[0];
                if (kb + kk + 1 < kend) v.y = p[1];
                if (kb + kk + 2 < kend) v.z = p[2];
            }
            out[i] = v;
        }
    };
    auto sttile = [&](float (*S)[128], const float4* v) {
#pragma unroll
        for (int i = 0; i < 2; i++) {
            int fid = tid * 2 + i;
            int r = fid >> 2, kk = (fid & 3) << 2;
            S[kk + 0][r] = v[i].x; S[kk + 1][r] = v[i].y;
            S[kk + 2][r] = v[i].z; S[kk + 3][r] = v[i].w;
        }
    };

    float4 pa[2], pb[2];
    ldtile(A, m0, k0, pa);
    ldtile(B, n0, k0, pb);
    sttile(As[0], pa);
    sttile(Bs[0], pb);
    __syncthreads();

    for (int kt = 0; kt < ntiles; kt++) {
        const int cur = kt & 1;
        if (kt + 1 < ntiles) {
            ldtile(A, m0, k0 + (kt + 1) * 16, pa);
            ldtile(B, n0, k0 + (kt + 1) * 16, pb);
        }
        const float (*Ac)[128] = As[cur];
        const float (*Bc)[128] = Bs[cur];
#pragma unroll
        for (int k = 0; k < 16; k++) {
            float4 a0 = *(const float4*)&Ac[k][rowg];
            float4 a1 = *(const float4*)&Ac[k][rowg + 4];
            float4 b0 = *(const float4*)&Bc[k][colg];
            float4 b1 = *(const float4*)&Bc[k][colg + 4];
            float a[8]  = {a0.x, a0.y, a0.z, a0.w, a1.x, a1.y, a1.z, a1.w};
            float bb[8] = {b0.x, b0.y, b0.z, b0.w, b1.x, b1.y, b1.z, b1.w};
#pragma unroll
            for (int i = 0; i < 8; i++)
#pragma unroll
                for (int j = 0; j < 8; j++)
                    acc[i][j] += a[i] * bb[j];
        }
        if (kt + 1 < ntiles) {
            sttile(As[1 - cur], pa);
            sttile(Bs[1 - cur], pb);
        }
        __syncthreads();
    }

#pragma unroll
    for (int i = 0; i < 8; i++) {
        const int m = m0 + rowg + i;
        float* cp = C + (size_t)m * N + n0 + colg;
#pragma unroll
        for (int j = 0; j < 8; j++) cp[j] = acc[i][j];
    }
}

// ---------------- sum split partials + fold biases ----------------
__global__ void reduce_splits(const float* __restrict__ bufs, float* __restrict__ C,
                              const float* __restrict__ b1, const float* __restrict__ b2,
                              int s, int N)
{
    int idx = blockIdx.x * blockDim.x + threadIdx.x;
    size_t base = (size_t)idx * 4;
    float4 acc = *(const float4*)(bufs + base);
    for (int i = 1; i < s; i++) {
        float4 v = *(const float4*)(bufs + (size_t)i * ((size_t)SEQ * G4) + base);
        acc.x += v.x; acc.y += v.y; acc.z += v.z; acc.w += v.w;
    }
    int n = (int)(base % (size_t)N);
    float4 u1 = *(const float4*)(b1 + n);
    float4 u2 = *(const float4*)(b2 + n);
    acc.x += u1.x + u2.x; acc.y += u1.y + u2.y;
    acc.z += u1.z + u2.z; acc.w += u1.w + u2.w;
    *(float4*)(C + base) = acc;
}

// ---------------- generic fp32 NT GEMM (GCN path, small N) ----------------
__global__ __launch_bounds__(256) void sgemm_nt(
    const float* __restrict__ A, const float* __restrict__ B,
    float* __restrict__ C, int M, int N, int K)
{
    __shared__ float As[16][128];
    __shared__ float Bs[16][64];
    const int tx = threadIdx.x, ty = threadIdx.y;
    const int tid = ty * 16 + tx;
    const int m0 = blockIdx.y * 128, n0 = blockIdx.x * 64;

    float acc[8][4];
#pragma unroll
    for (int i = 0; i < 8; i++)
#pragma unroll
        for (int j = 0; j < 4; j++) acc[i][j] = 0.f;

    const bool k4ok = ((K & 3) == 0);
    const int ntiles = (K + 15) >> 4;

    for (int kt = 0; kt < ntiles; kt++) {
        const int kb = kt * 16;
#pragma unroll
        for (int i = 0; i < 2; i++) {
            int fid = tid * 2 + i;
            int r = fid >> 2;
            int kk = (fid & 3) << 2;
            float4 v = make_float4(0.f, 0.f, 0.f, 0.f);
            if (m0 + r < M) {
                const float* ap = A + (size_t)(m0 + r) * K + kb + kk;
                if (k4ok && kb + kk + 3 < K) v = *(const float4*)ap;
                else {
                    if (kb + kk + 0 < K) v.x = ap[0];
                    if (kb + kk + 1 < K) v.y = ap[1];
                    if (kb + kk + 2 < K) v.z = ap[2];
                    if (kb + kk + 3 < K) v.w = ap[3];
                }
            }
            As[kk + 0][r] = v.x; As[kk + 1][r] = v.y;
            As[kk + 2][r] = v.z; As[kk + 3][r] = v.w;
        }
        {
            int r = tid >> 2;
            int kk = (tid & 3) << 2;
            float4 v = make_float4(0.f, 0.f, 0.f, 0.f);
            if (n0 + r < N) {
                const float* bp = B + (size_t)(n0 + r) * K + kb + kk;
                if (k4ok && kb + kk + 3 < K) v = *(const float4*)bp;
                else {
                    if (kb + kk + 0 < K) v.x = bp[0];
                    if (kb + kk + 1 < K) v.y = bp[1];
                    if (kb + kk + 2 < K) v.z = bp[2];
                    if (kb + kk + 3 < K) v.w = bp[3];
                }
            }
            Bs[kk + 0][r] = v.x; Bs[kk + 1][r] = v.y;
            Bs[kk + 2][r] = v.z; Bs[kk + 3][r] = v.w;
        }
        __syncthreads();
#pragma unroll
        for (int k = 0; k < 16; k++) {
            float4 b4 = *(const float4*)&Bs[k][tx * 4];
            float4 a0 = *(const float4*)&As[k][ty * 8];
            float4 a1 = *(const float4*)&As[k][ty * 8 + 4];
            float a[8] = {a0.x, a0.y, a0.z, a0.w, a1.x, a1.y, a1.z, a1.w};
            float bb[4] = {b4.x, b4.y, b4.z, b4.w};
#pragma unroll
            for (int i = 0; i < 8; i++)
#pragma unroll
                for (int j = 0; j < 4; j++)
                    acc[i][j] += a[i] * bb[j];
        }
        __syncthreads();
    }
#pragma unroll
    for (int i = 0; i < 8; i++) {
        int m = m0 + ty * 8 + i;
        if (m >= M) continue;
#pragma unroll
        for (int j = 0; j < 4; j++) {
            int n = n0 + tx * 4 + j;
            if (n < N) C[(size_t)m * N + n] = acc[i][j];
        }
    }
}

// ---------------- sentinel fill: seq_out <- 2.0f (SEQ*HDIM floats) ----------------
__global__ void fill_sentinel(float* __restrict__ p) {
    int i = blockIdx.x * blockDim.x + threadIdx.x;   // SEQ*HDIM/4 threads
    float4 s = make_float4(2.f, 2.f, 2.f, 2.f);
    ((float4*)p)[i] = s;
}

// ---------------- persistent LSTM recurrence (sentinel-valued h: signal == payload) ----------------
// 128 CTAs x 640 threads. CTA k owns hidden units [5k,5k+5); warp w: unit u=w>>2,
// gate g=w&3, Whh row in registers. |h|<1 strictly, so 2.0f marks "not yet written".
// Producers: st.relaxed.gpu of h is the publication (no counter, no fence).
// Consumers: thread tid polls ITS OWN seq_out[t-1][tid] until != 2.0f — detection and
// payload share one L2 round trip; per-address coherence makes fences unnecessary.
__global__ __launch_bounds__(640, 1) void lstm_rec(
    const float* __restrict__ xW,   // [1024, 2560] (biases folded in)
    const float* __restrict__ Whh,  // [2560, 640]
    float* __restrict__ seq_out)    // [1024, 640] pre-filled with 2.0f
{
    __shared__ float h_s[640];
    __shared__ float dots[5][4];
    __shared__ float c_s[5];

    const int tid = threadIdx.x;
    const int w = tid >> 5, l = tid & 31;
    const int k = blockIdx.x;
    const int u = w >> 2;
    const int gsel = w & 3;
    const int uglob = 5 * k + u;
    const int row = gsel * 640 + uglob;

    float wreg[20];
    const float* wp = Whh + (size_t)row * 640 + 20 * l;
#pragma unroll
    for (int i = 0; i < 20; i++) wreg[i] = wp[i];
    if (tid < 5) c_s[tid] = 0.f;
    __syncthreads();

    for (int t = 0; t < SEQ; t++) {
        // warp-0 gate lanes prefetch xW operands before the wait (off critical path)
        float xg0 = 0.f, xg1 = 0.f, xg2 = 0.f, xg3 = 0.f;
        if (tid < 5) {
            const float* xwt = xW + (size_t)t * G4 + 5 * k + tid;
            xg0 = __ldg(xwt);
            xg1 = __ldg(xwt + 640);
            xg2 = __ldg(xwt + 1280);
            xg3 = __ldg(xwt + 1920);
        }

        float acc = 0.f;
        if (t > 0) {
            // poll own h value: first load is the mandatory payload load; only
            // unsatisfied lanes loop (SIMT predication limits the retry storm).
            const float* hp_g = seq_out + (size_t)(t - 1) * 640 + tid;
            float hv;
            do {
                asm volatile("ld.relaxed.gpu.global.f32 %0, [%1];"
                             : "=f"(hv) : "l"(hp_g) : "memory");
            } while (__float_as_uint(hv) == SENTINEL_U);
            h_s[tid] = hv;
            __syncthreads();
            const float4* hp = (const float4*)(h_s + 20 * l);
#pragma unroll
            for (int i = 0; i < 5; i++) {
                float4 v = hp[i];
                acc += wreg[4 * i + 0] * v.x + wreg[4 * i + 1] * v.y
                     + wreg[4 * i + 2] * v.z + wreg[4 * i + 3] * v.w;
            }
        }
#pragma unroll
        for (int off = 16; off > 0; off >>= 1)
            acc += __shfl_down_sync(0xffffffffu, acc, off);
        if (l == 0) dots[u][gsel] = acc;
        __syncthreads();

        if (w == 0 && l < 5) {
            const int uu = l;
            const int ug = 5 * k + uu;
            float gi = xg0 + dots[uu][0];
            float gf = xg1 + dots[uu][1];
            float gg = xg2 + dots[uu][2];
            float go = xg3 + dots[uu][3];
            float iv = fsigmoid(gi);
            float fv = fsigmoid(gf);
            float gv = ftanh(gg);
            float ov = fsigmoid(go);
            float c = fv * c_s[uu] + iv * gv;
            c_s[uu] = c;
            float hv = ov * ftanh(c);
            asm volatile("st.relaxed.gpu.global.f32 [%0], %1;"
                         :: "l"(seq_out + (size_t)t * 640 + ug), "f"(hv) : "memory");
        }
        // non-gate warps park at the next iteration's __syncthreads (after their
        // own poll); h_s/dots rewrites at t+1 happen only after warp 0 passes it.
    }
}

// ---------------- graph prep ----------------
__global__ void zero_deg(int* deg) {
    int i = blockIdx.x * blockDim.x + threadIdx.x;
    if (i < NNODES) deg[i] = 0;
}
__global__ void count_deg(const int* __restrict__ dst, int* deg) {
    int e = blockIdx.x * blockDim.x + threadIdx.x;
    if (e < NEDGES) atomicAdd(&deg[dst[e]], 1);
}
__global__ void finalize_deg(const int* __restrict__ deg, float* dinv, float* selfnorm) {
    int i = blockIdx.x * blockDim.x + threadIdx.x;
    if (i < NNODES) {
        float d = rsqrtf((float)(deg[i] + 1));
        dinv[i] = d;
        selfnorm[i] = d * d;
    }
}
__global__ void edge_norm(const int* __restrict__ src, const int* __restrict__ dst,
                          const float* __restrict__ dinv, float* enorm) {
    int e = blockIdx.x * blockDim.x + threadIdx.x;
    if (e < NEDGES) enorm[e] = dinv[src[e]] * dinv[dst[e]];
}
__global__ void transpose_k(const float* __restrict__ W, float* __restrict__ Wt,
                            int Cin, int Cout) {
    int idx = blockIdx.x * blockDim.x + threadIdx.x;
    if (idx < Cin * Cout) {
        int i = idx / Cout, o = idx % Cout;
        Wt[o * Cin + i] = W[idx];
    }
}

// ---------------- GCN scatter ----------------
__global__ void scatter_init(const float* __restrict__ h, const float* __restrict__ selfnorm,
                             float* __restrict__ y, int C) {
    int idx = blockIdx.x * blockDim.x + threadIdx.x;
    if (idx < NNODES * C) {
        int i = idx / C;
        y[idx] = selfnorm[i] * h[idx];
    }
}
__global__ void scatter_edges(const float* __restrict__ h, const float* __restrict__ enorm,
                              const int* __restrict__ src, const int* __restrict__ dst,
                              float* __restrict__ y, int C) {
    int idx = blockIdx.x * blockDim.x + threadIdx.x;
    if (idx < NEDGES * C) {
        int e = idx / C, c = idx - e * C;
        atomicAdd(&y[dst[e] * C + c], enorm[e] * h[src[e] * C + c]);
    }
}

// ---------------- bias + leaky + batchnorm (per-column CTA) ----------------
__global__ void bias_leaky_bn(const float* __restrict__ y, const float* __restrict__ b,
                              float* __restrict__ out, int C) {
    const int c = blockIdx.x;
    const int tid = threadIdx.x;
    const float bias = b[c];
    float s = 0.f, sq = 0.f;
    for (int r = tid; r < NNODES; r += 256) {
        float v = y[r * C + c] + bias;
        v = (v > 0.f) ? v : 0.01f * v;
        s += v; sq += v * v;
    }
    __shared__ float rs[256], rq[256];
    rs[tid] = s; rq[tid] = sq;
    __syncthreads();
    for (int o = 128; o > 0; o >>= 1) {
        if (tid < o) { rs[tid] += rs[tid + o]; rq[tid] += rq[tid + o]; }
        __syncthreads();
    }
    float mean = rs[0] * (1.f / NNODES);
    float var = rq[0] * (1.f / NNODES) - mean * mean;
    float rstd = rsqrtf(var + 1e-5f);
    for (int r = tid; r < NNODES; r += 256) {
        float v = y[r * C + c] + bias;
        v = (v > 0.f) ? v : 0.01f * v;
        out[r * C + c] = (v - mean) * rstd;
    }
}

// ---------------- head: segment sum + concat + 3 FC ----------------
__global__ void head_kernel(const float* __restrict__ x,
                            const float* __restrict__ gender, const float* __restrict__ handed,
                            const float* __restrict__ W1, const float* __restrict__ b1,
                            const float* __restrict__ W2, const float* __restrict__ b2,
                            const float* __restrict__ W3, const float* __restrict__ b3,
                            float* __restrict__ out) {
    const int b = blockIdx.x;
    const int tid = threadIdx.x;
    __shared__ float feat[52];
    __shared__ float y1[32], y2[16];
    if (tid < 50) {
        float s = 0.f;
        for (int r = 0; r < 64; r++) s += x[(b * 64 + r) * 50 + tid];
        feat[tid] = s;
    }
    if (tid == 50) feat[50] = gender[b];
    if (tid == 51) feat[51] = handed[b];
    __syncthreads();
    if (tid < 32) {
        float s = b1[tid];
        for (int i = 0; i < 52; i++) s += feat[i] * W1[tid * 52 + i];
        y1[tid] = s;
    }
    __syncthreads();
    if (tid < 16) {
        float s = b2[tid];
        for (int i = 0; i < 32; i++) s += y1[i] * W2[tid * 32 + i];
        y2[tid] = s;
    }
    __syncthreads();
    if (tid == 0) {
        float s = b3[0];
        for (int i = 0; i < 16; i++) s += y2[i] * W3[i];
        out[b] = s;
    }
}

// ---------------- host ----------------
extern "C" void kernel_launch(void* const* d_in, const int* in_sizes, int n_in,
                              void* d_out, int out_size) {
    const float* x_in   = (const float*)d_in[0];
    const int*   eidx   = (const int*)d_in[1];
    const float* gender = (const float*)d_in[2];
    const float* handed = (const float*)d_in[3];
    const float* Wih[3] = {(const float*)d_in[4], (const float*)d_in[8],  (const float*)d_in[12]};
    const float* Whh[3] = {(const float*)d_in[5], (const float*)d_in[9],  (const float*)d_in[13]};
    const float* bih[3] = {(const float*)d_in[6], (const float*)d_in[10], (const float*)d_in[14]};
    const float* bhh[3] = {(const float*)d_in[7], (const float*)d_in[11], (const float*)d_in[15]};
    const float* gcnW[4] = {(const float*)d_in[16], (const float*)d_in[18], (const float*)d_in[20], (const float*)d_in[22]};
    const float* gcnB[4] = {(const float*)d_in[17], (const float*)d_in[19], (const float*)d_in[21], (const float*)d_in[23]};
    const float* fcW[3] = {(const float*)d_in[24], (const float*)d_in[26], (const float*)d_in[28]};
    const float* fcB[3] = {(const float*)d_in[25], (const float*)d_in[27], (const float*)d_in[29]};

    float *xWp, *xW, *bufA, *bufB, *gh, *gy, *Wt, *dinv, *selfnorm, *enorm;
    int* deg;
    cudaGetSymbolAddress((void**)&xWp, g_xWp);
    cudaGetSymbolAddress((void**)&xW, g_xW);
    cudaGetSymbolAddress((void**)&bufA, g_bufA);
    cudaGetSymbolAddress((void**)&bufB, g_bufB);
    cudaGetSymbolAddress((void**)&gh, g_gh);
    cudaGetSymbolAddress((void**)&gy, g_gy);
    cudaGetSymbolAddress((void**)&Wt, g_Wt);
    cudaGetSymbolAddress((void**)&deg, g_deg);
    cudaGetSymbolAddress((void**)&dinv, g_dinv);
    cudaGetSymbolAddress((void**)&selfnorm, g_selfnorm);
    cudaGetSymbolAddress((void**)&enorm, g_enorm);

    const int* src = eidx;
    const int* dst = eidx + NEDGES;
    dim3 tb(16, 16);
    const int nred = (SEQ * G4) / 4 / 256;      // 2560 CTAs, exact
    const int nfill = (SEQ * HDIM) / 4 / 256;   // 640 CTAs, exact

    // ---- LSTM layer 0 (K=8500, split-K s=8, Kc=1064 multiple of 4) ----
    sgemm128_split<<<dim3(G4 / 128, SEQ / 128, 8), 256>>>(x_in, Wih[0], xWp, SEQ, G4, 8500, 1064);
    reduce_splits<<<nred, 256>>>(xWp, xW, bih[0], bhh[0], 8, G4);
    fill_sentinel<<<nfill, 256>>>(bufA);
    lstm_rec<<<NCTA_REC, 640>>>(xW, Whh[0], bufA);

    // ---- LSTM layer 1 (K=640, split-K s=2) ----
    sgemm128_split<<<dim3(G4 / 128, SEQ / 128, 2), 256>>>(bufA, Wih[1], xWp, SEQ, G4, HDIM, 320);
    reduce_splits<<<nred, 256>>>(xWp, xW, bih[1], bhh[1], 2, G4);
    fill_sentinel<<<nfill, 256>>>(bufB);
    lstm_rec<<<NCTA_REC, 640>>>(xW, Whh[1], bufB);

    // ---- LSTM layer 2 ----
    sgemm128_split<<<dim3(G4 / 128, SEQ / 128, 2), 256>>>(bufB, Wih[2], xWp, SEQ, G4, HDIM, 320);
    reduce_splits<<<nred, 256>>>(xWp, xW, bih[2], bhh[2], 2, G4);
    fill_sentinel<<<nfill, 256>>>(bufA);
    lstm_rec<<<NCTA_REC, 640>>>(xW, Whh[2], bufA);

    // ---- graph prep ----
    zero_deg<<<4, 256>>>(deg);
    count_deg<<<NEDGES / 256, 256>>>(dst, deg);
    finalize_deg<<<4, 256>>>(deg, dinv, selfnorm);
    edge_norm<<<NEDGES / 256, 256>>>(src, dst, dinv, enorm);

    // ---- GCN layers ----
    const int cins[4]  = {640, 320, 180, 90};
    const int couts[4] = {320, 180, 90, 50};
    float* xcur = bufA;
    float* xnext = bufB;
    for (int l = 0; l < 4; l++) {
        int Cin = cins[l], Cout = couts[l];
        transpose_k<<<(Cin * Cout + 255) / 256, 256>>>(gcnW[l], Wt, Cin, Cout);
        sgemm_nt<<<dim3((Cout + 63) / 64, NNODES / 128), tb>>>(xcur, Wt, gh, NNODES, Cout, Cin);
        scatter_init<<<(NNODES * Cout + 255) / 256, 256>>>(gh, selfnorm, gy, Cout);
        scatter_edges<<<(NEDGES * Cout + 255) / 256, 256>>>(gh, enorm, src, dst, gy, Cout);
        bias_leaky_bn<<<Cout, 256>>>(gy, gcnB[l], xnext, Cout);
        float* tmp = xcur; xcur = xnext; xnext = tmp;
    }

    // ---- head ----
    head_kernel<<<BSZ, 64>>>(xcur, gender, handed,
                             fcW[0], fcB[0], fcW[1], fcB[1], fcW[2], fcB[2],
                             (float*)d_out);
}